// round 2
// baseline (speedup 1.0000x reference)
#include <cuda_runtime.h>

#define NB   1024      // graphs
#define NPG  64        // nodes per graph
#define EPG  1024      // edges per graph
#define NEPG 256       // non-edges per graph
#define NN   (NB*NPG)      // 65536 nodes
#define NEDGE (NB*EPG)     // 1048576 edges
#define EMB  64
#define HID  128
#define NCAT 100
#define NET  4
#define NOUT 101
#define OUTW (1 + NPG*NOUT + NEPG)   // 6721

typedef unsigned long long ull;

// ---------------- scratch (device globals, no allocation) ----------------
__device__ float g_P1[NCAT*HID];
__device__ float g_ea1[NET];
__device__ float g_ea2[NET];
__device__ float g_h1[(size_t)NN*HID];   // GAT1 output (relu)
__device__ float g_hw[(size_t)NN*HID];   // h1 @ c2_w
__device__ float g_h2[(size_t)NN*HID];   // GAT2 output
__device__ float g_t [(size_t)NN*HID];   // relu(h2 @ n_w1 + n_b1)
__device__ float g_q [(size_t)NN*HID];   // h2 @ e_w1
__device__ float g_pool[NB*HID];         // per-graph sum of h2

// ---------------- f32x2 helpers ----------------
__device__ __forceinline__ ull pk2(float lo, float hi) {
    ull r; asm("mov.b64 %0, {%1,%2};" : "=l"(r) : "f"(lo), "f"(hi)); return r;
}
__device__ __forceinline__ void fma2(ull& d, ull a, ull b) {
    asm("fma.rn.f32x2 %0, %1, %2, %0;" : "+l"(d) : "l"(a), "l"(b));
}
__device__ __forceinline__ void upk2(ull v, float& lo, float& hi) {
    asm("mov.b64 {%0,%1}, %2;" : "=f"(lo), "=f"(hi) : "l"(v));
}

// ---------------- prep: P1 = node_tab@c1_w ; ea tables ----------------
__global__ void prep_kernel(const float* __restrict__ node_tab,
                            const float* __restrict__ edge_tab,
                            const float* __restrict__ c1_w,
                            const float* __restrict__ c1_we,
                            const float* __restrict__ c1_ae,
                            const float* __restrict__ c2_we,
                            const float* __restrict__ c2_ae) {
    __shared__ float red[HID];
    int bid = blockIdx.x, tid = threadIdx.x;
    if (bid < NCAT) {
        float acc = 0.f;
        #pragma unroll 8
        for (int k = 0; k < EMB; k++) acc += node_tab[bid*EMB + k] * c1_w[k*HID + tid];
        g_P1[bid*HID + tid] = acc;
    } else {
        for (int combo = 0; combo < 2*NET; combo++) {
            int layer = combo >> 2, t = combo & 3;
            const float* We = layer ? c2_we : c1_we;
            const float* ae = layer ? c2_ae : c1_ae;
            float acc = 0.f;
            #pragma unroll 8
            for (int k = 0; k < EMB; k++) acc += edge_tab[t*EMB + k] * We[k*HID + tid];
            red[tid] = acc * ae[tid];
            __syncthreads();
            if (tid < 32) {
                float s = red[tid] + red[tid+32] + red[tid+64] + red[tid+96];
                #pragma unroll
                for (int o = 16; o; o >>= 1) s += __shfl_down_sync(0xffffffffu, s, o);
                if (tid == 0) { if (layer) g_ea2[t] = s; else g_ea1[t] = s; }
            }
            __syncthreads();
        }
    }
}

// ---------------- per-graph GAT layer ----------------
// layer==0: features = P1[x[node]]; relu output -> g_h1
// layer==1: features = g_hw rows;   output -> g_h2 ; also per-graph pool
__global__ __launch_bounds__(256) void gat_kernel(
    const int* __restrict__ x,
    const int* __restrict__ edge_index,
    const int* __restrict__ edge_attr,
    const float* __restrict__ a_s,
    const float* __restrict__ a_d,
    const float* __restrict__ bias,
    int layer) {
    __shared__ float shh[NPG][HID];        // 32 KB node features (transformed)
    __shared__ float slog[EPG];            // edge logits (then exp)
    __shared__ unsigned short ssrc[EPG];   // sorted local src
    __shared__ float shs[NPG], shd[NPG];
    __shared__ int cnt[NPG], off[NPG], woff[NPG];
    __shared__ float shas[HID], shad[HID], shb[HID];
    __shared__ float shea[NET];
    __shared__ int codes[NPG];
    __shared__ float shpool[HID];

    int g = blockIdx.x, tid = threadIdx.x;
    int nbase = g * NPG, ebase = g * EPG;
    int lane = tid & 31, w = tid >> 5;

    if (tid < HID) { shas[tid] = a_s[tid]; shad[tid] = a_d[tid]; shb[tid] = bias[tid]; shpool[tid] = 0.f; }
    if (tid < NET) shea[tid] = layer ? g_ea2[tid] : g_ea1[tid];
    if (tid < NPG) { cnt[tid] = 0; if (layer == 0) codes[tid] = x[nbase + tid]; }
    __syncthreads();

    // load transformed node features into SMEM
    if (layer == 0) {
        for (int i = tid; i < NPG * (HID/4); i += 256) {
            int r = i >> 5, qq = i & 31;   // 32 float4 per row
            ((float4*)shh[r])[qq] = ((const float4*)(g_P1 + codes[r]*HID))[qq];
        }
    } else {
        const float4* src4 = (const float4*)(g_hw + (size_t)nbase * HID);
        for (int i = tid; i < NPG * (HID/4); i += 256)
            ((float4*)shh)[i] = src4[i];
    }
    __syncthreads();

    // per-node attention scalars s,d
    for (int r = w; r < NPG; r += 8) {
        float ss = 0.f, dd = 0.f;
        #pragma unroll
        for (int u = 0; u < 4; u++) {
            int c = lane + 32*u;
            float hv = shh[r][c];
            ss += hv * shas[c]; dd += hv * shad[c];
        }
        #pragma unroll
        for (int o = 16; o; o >>= 1) {
            ss += __shfl_down_sync(0xffffffffu, ss, o);
            dd += __shfl_down_sync(0xffffffffu, dd, o);
        }
        if (lane == 0) { shs[r] = ss; shd[r] = dd; }
    }

    // count edges per local dst
    for (int e = tid; e < EPG; e += 256) {
        int dl = edge_index[NEDGE + ebase + e] & (NPG - 1);
        atomicAdd(&cnt[dl], 1);
    }
    __syncthreads();
    if (tid == 0) {
        int run = 0;
        for (int i = 0; i < NPG; i++) { off[i] = run; woff[i] = run; run += cnt[i]; }
    }
    __syncthreads();

    // compute logits + counting-sort by dst
    for (int e = tid; e < EPG; e += 256) {
        int sl = edge_index[ebase + e] & (NPG - 1);
        int dl = edge_index[NEDGE + ebase + e] & (NPG - 1);
        int at = edge_attr[ebase + e];
        float lg = shs[sl] + shd[dl] + shea[at];
        lg = lg > 0.f ? lg : 0.2f * lg;              // leaky_relu(0.2)
        int pos = atomicAdd(&woff[dl], 1);
        slog[pos] = lg;
        ssrc[pos] = (unsigned short)sl;
    }
    __syncthreads();

    // per-dst softmax + weighted aggregation (one warp owns dst, 8 dsts/warp)
    float pacc[4] = {0.f, 0.f, 0.f, 0.f};
    for (int dl = w; dl < NPG; dl += 8) {
        int st = off[dl], cn = cnt[dl];
        float m = -1e30f;
        for (int j = lane; j < cn; j += 32) m = fmaxf(m, slog[st + j]);
        #pragma unroll
        for (int o = 16; o; o >>= 1) m = fmaxf(m, __shfl_xor_sync(0xffffffffu, m, o));
        float den = 0.f;
        for (int j = lane; j < cn; j += 32) {
            float ex = expf(slog[st + j] - m);
            slog[st + j] = ex;
            den += ex;
        }
        #pragma unroll
        for (int o = 16; o; o >>= 1) den += __shfl_xor_sync(0xffffffffu, den, o);
        __syncwarp();
        float inv = 1.f / (den + 1e-16f);
        float acc0 = 0.f, acc1 = 0.f, acc2 = 0.f, acc3 = 0.f;
        for (int j = 0; j < cn; j++) {
            float al = slog[st + j] * inv;
            const float* hr = shh[ssrc[st + j]];
            acc0 += al * hr[lane];
            acc1 += al * hr[lane + 32];
            acc2 += al * hr[lane + 64];
            acc3 += al * hr[lane + 96];
        }
        float* outp = (layer == 0 ? g_h1 : g_h2) + (size_t)(nbase + dl) * HID;
        float v0 = acc0 + shb[lane];
        float v1 = acc1 + shb[lane + 32];
        float v2 = acc2 + shb[lane + 64];
        float v3 = acc3 + shb[lane + 96];
        if (layer == 0) { v0 = fmaxf(v0, 0.f); v1 = fmaxf(v1, 0.f); v2 = fmaxf(v2, 0.f); v3 = fmaxf(v3, 0.f); }
        outp[lane] = v0; outp[lane + 32] = v1; outp[lane + 64] = v2; outp[lane + 96] = v3;
        if (layer) { pacc[0] += v0; pacc[1] += v1; pacc[2] += v2; pacc[3] += v3; }
    }
    if (layer) {
        atomicAdd(&shpool[lane],      pacc[0]);
        atomicAdd(&shpool[lane + 32], pacc[1]);
        atomicAdd(&shpool[lane + 64], pacc[2]);
        atomicAdd(&shpool[lane + 96], pacc[3]);
        __syncthreads();
        if (tid < HID) g_pool[g * HID + tid] = shpool[tid];
    }
}

// ---------------- GEMM: out = (relu?)(A[N,128] @ W[128,CW] + bias) ----------------
// sel: 0: A=g_h1 -> g_hw | 1: A=g_h2 -> g_t | 2: A=g_h2 -> g_q | 3: A=g_t -> outParam (mode1)
__global__ __launch_bounds__(256) void gemm_kernel(
    const float* __restrict__ W, const float* __restrict__ bias,
    float* __restrict__ outParam, int CW, int doRelu, int mode, int sel) {
    __shared__ float As[64][36];     // padded row stride (no bank conflicts)
    __shared__ float Ws[32][HID];

    const float* A; float* out;
    if (sel == 0)      { A = g_h1; out = g_hw; }
    else if (sel == 1) { A = g_h2; out = g_t; }
    else if (sel == 2) { A = g_h2; out = g_q; }
    else               { A = g_t;  out = outParam; }

    int tid = threadIdx.x;
    int tx = tid & 15, ty = tid >> 4;        // 16 x 16 thread grid
    int rowbase = blockIdx.x * 64;

    ull acc[4][4];
    #pragma unroll
    for (int i = 0; i < 4; i++)
        #pragma unroll
        for (int p = 0; p < 4; p++) acc[i][p] = 0ull;

    for (int k0 = 0; k0 < HID; k0 += 32) {
        // stage A chunk: 64 rows x 32 k
        for (int i = tid; i < 512; i += 256) {
            int r = i >> 3, qf = i & 7;
            float4 v = ((const float4*)(A + (size_t)(rowbase + r) * HID + k0))[qf];
            *((float4*)&As[r][qf * 4]) = v;
        }
        // stage W chunk: 32 k x 128 cols (zero-pad cols >= CW)
        for (int i = tid; i < 32 * HID; i += 256) {
            int kk = i >> 7, j = i & 127;
            Ws[kk][j] = (j < CW) ? W[(size_t)(k0 + kk) * CW + j] : 0.f;
        }
        __syncthreads();
        #pragma unroll
        for (int kk = 0; kk < 32; kk++) {
            float a0 = As[ty*4 + 0][kk];
            float a1 = As[ty*4 + 1][kk];
            float a2 = As[ty*4 + 2][kk];
            float a3 = As[ty*4 + 3][kk];
            ull pa0 = pk2(a0, a0), pa1 = pk2(a1, a1), pa2 = pk2(a2, a2), pa3 = pk2(a3, a3);
            float4 b0 = *(const float4*)&Ws[kk][tx * 8];
            float4 b1 = *(const float4*)&Ws[kk][tx * 8 + 4];
            ull pb0 = pk2(b0.x, b0.y), pb1 = pk2(b0.z, b0.w);
            ull pb2 = pk2(b1.x, b1.y), pb3 = pk2(b1.z, b1.w);
            fma2(acc[0][0], pa0, pb0); fma2(acc[0][1], pa0, pb1); fma2(acc[0][2], pa0, pb2); fma2(acc[0][3], pa0, pb3);
            fma2(acc[1][0], pa1, pb0); fma2(acc[1][1], pa1, pb1); fma2(acc[1][2], pa1, pb2); fma2(acc[1][3], pa1, pb3);
            fma2(acc[2][0], pa2, pb0); fma2(acc[2][1], pa2, pb1); fma2(acc[2][2], pa2, pb2); fma2(acc[2][3], pa2, pb3);
            fma2(acc[3][0], pa3, pb0); fma2(acc[3][1], pa3, pb1); fma2(acc[3][2], pa3, pb2); fma2(acc[3][3], pa3, pb3);
        }
        __syncthreads();
    }

    #pragma unroll
    for (int i = 0; i < 4; i++) {
        int row = rowbase + ty * 4 + i;
        #pragma unroll
        for (int p = 0; p < 4; p++) {
            float lo, hi; upk2(acc[i][p], lo, hi);
            int c0 = tx * 8 + 2 * p, c1 = c0 + 1;
            if (mode == 0) {
                if (bias) { lo += bias[c0]; hi += bias[c1]; }
                if (doRelu) { lo = fmaxf(lo, 0.f); hi = fmaxf(hi, 0.f); }
                out[(size_t)row * HID + c0] = lo;
                out[(size_t)row * HID + c1] = hi;
            } else {  // addnode layout: out[g*OUTW + 1 + l*NOUT + c], c < NOUT
                int gph = row >> 6, l = row & 63;
                size_t base = (size_t)gph * OUTW + 1 + (size_t)l * NOUT;
                if (c0 < CW) out[base + c0] = lo + bias[c0];
                if (c1 < CW) out[base + c1] = hi + bias[c1];
            }
        }
    }
}

// ---------------- final: stop head + addedge head ----------------
__global__ __launch_bounds__(256) void final_kernel(
    const int* __restrict__ non_edges,
    const float* __restrict__ s_w1, const float* __restrict__ s_b1,
    const float* __restrict__ s_w2, const float* __restrict__ s_b2,
    const float* __restrict__ e_b1, const float* __restrict__ e_w2,
    const float* __restrict__ e_b2,
    float* __restrict__ out) {
    __shared__ float shq[NPG][HID];
    __shared__ float sheb[HID], shw2[HID], shp[HID], shz[HID];

    int g = blockIdx.x, tid = threadIdx.x;
    int lane = tid & 31, w = tid >> 5;

    const float4* src4 = (const float4*)(g_q + (size_t)g * NPG * HID);
    for (int i = tid; i < NPG * (HID/4); i += 256) ((float4*)shq)[i] = src4[i];
    if (tid < HID) { sheb[tid] = e_b1[tid]; shw2[tid] = e_w2[tid]; shp[tid] = g_pool[g * HID + tid]; }
    __syncthreads();

    // stop MLP hidden layer
    if (tid < HID) {
        float acc = s_b1[tid];
        #pragma unroll 8
        for (int k = 0; k < HID; k++) acc += shp[k] * s_w1[k * HID + tid];
        shz[tid] = fmaxf(acc, 0.f);
    }
    __syncthreads();

    if (w == 0) {
        float s_ = 0.f;
        #pragma unroll
        for (int u = 0; u < 4; u++) s_ += shz[lane + 32*u] * s_w2[lane + 32*u];
        #pragma unroll
        for (int o = 16; o; o >>= 1) s_ += __shfl_down_sync(0xffffffffu, s_, o);
        if (lane == 0) out[(size_t)g * OUTW] = s_ + s_b2[0];
    }

    int nebase = g * NEPG;
    for (int ne = w; ne < NEPG; ne += 8) {
        int u = non_edges[(size_t)(nebase + ne) * 2]     & (NPG - 1);
        int v = non_edges[(size_t)(nebase + ne) * 2 + 1] & (NPG - 1);
        float acc = 0.f;
        #pragma unroll
        for (int uu = 0; uu < 4; uu++) {
            int c = lane + 32 * uu;
            float tv = shq[u][c] + shq[v][c] + sheb[c];
            tv = fmaxf(tv, 0.f);
            acc += tv * shw2[c];
        }
        #pragma unroll
        for (int o = 16; o; o >>= 1) acc += __shfl_down_sync(0xffffffffu, acc, o);
        if (lane == 0) out[(size_t)g * OUTW + 1 + NPG * NOUT + ne] = acc + e_b2[0];
    }
}

// ---------------- launch ----------------
extern "C" void kernel_launch(void* const* d_in, const int* in_sizes, int n_in,
                              void* d_out, int out_size) {
    const float* node_tab = (const float*)d_in[0];
    const float* edge_tab = (const float*)d_in[1];
    const float* c1_w  = (const float*)d_in[2];
    const float* c1_we = (const float*)d_in[3];
    const float* c1_as = (const float*)d_in[4];
    const float* c1_ad = (const float*)d_in[5];
    const float* c1_ae = (const float*)d_in[6];
    const float* c1_b  = (const float*)d_in[7];
    const float* c2_w  = (const float*)d_in[8];
    const float* c2_we = (const float*)d_in[9];
    const float* c2_as = (const float*)d_in[10];
    const float* c2_ad = (const float*)d_in[11];
    const float* c2_ae = (const float*)d_in[12];
    const float* c2_b  = (const float*)d_in[13];
    const float* s_w1  = (const float*)d_in[14];
    const float* s_b1  = (const float*)d_in[15];
    const float* s_w2  = (const float*)d_in[16];
    const float* s_b2  = (const float*)d_in[17];
    const float* n_w1  = (const float*)d_in[18];
    const float* n_b1  = (const float*)d_in[19];
    const float* n_w2  = (const float*)d_in[20];
    const float* n_b2  = (const float*)d_in[21];
    const float* e_w1  = (const float*)d_in[22];
    const float* e_b1  = (const float*)d_in[23];
    const float* e_w2  = (const float*)d_in[24];
    const float* e_b2  = (const float*)d_in[25];
    const int* x          = (const int*)d_in[26];
    const int* edge_index = (const int*)d_in[27];
    const int* edge_attr  = (const int*)d_in[28];
    const int* non_edges  = (const int*)d_in[29];
    float* out = (float*)d_out;

    // 1) tiny precompute: P1 lookup table + edge-attr logit tables
    prep_kernel<<<NCAT + 1, HID>>>(node_tab, edge_tab, c1_w, c1_we, c1_ae, c2_we, c2_ae);
    // 2) GAT layer 1 (per-graph, fully in SMEM) -> g_h1
    gat_kernel<<<NB, 256>>>(x, edge_index, edge_attr, c1_as, c1_ad, c1_b, 0);
    // 3) g_hw = g_h1 @ c2_w
    gemm_kernel<<<NN / 64, 256>>>(c2_w, nullptr, nullptr, HID, 0, 0, 0);
    // 4) GAT layer 2 -> g_h2 (+ per-graph pool)
    gat_kernel<<<NB, 256>>>(x, edge_index, edge_attr, c2_as, c2_ad, c2_b, 1);
    // 5) g_t = relu(g_h2 @ n_w1 + n_b1)
    gemm_kernel<<<NN / 64, 256>>>(n_w1, n_b1, nullptr, HID, 1, 0, 1);
    // 6) g_q = g_h2 @ e_w1
    gemm_kernel<<<NN / 64, 256>>>(e_w1, nullptr, nullptr, HID, 0, 0, 2);
    // 7) addnode = g_t @ n_w2 + n_b2 -> strided into d_out
    gemm_kernel<<<NN / 64, 256>>>(n_w2, n_b2, out, NOUT, 0, 1, 3);
    // 8) stop head + addedge head -> d_out
    final_kernel<<<NB, 256>>>(non_edges, s_w1, s_b1, s_w2, s_b2, e_b1, e_w2, e_b2, out);
}

// round 4
// speedup vs baseline: 1.7758x; 1.7758x over previous
#include <cuda_runtime.h>
#include <cuda_bf16.h>
#include <cstdint>

#define NB   1024
#define NPG  64
#define EPG  1024
#define NEPG 256
#define NN   (NB*NPG)
#define NEDGE (NB*EPG)
#define EMB  64
#define HID  128
#define NCAT 100
#define NET  4
#define NOUT 101
#define OUTW (1 + NPG*NOUT + NEPG)   // 6721

typedef unsigned long long ull;
typedef unsigned int u32;

// ---------------- scratch ----------------
__device__ float g_P1[NCAT*HID];
__device__ float g_ea1[NET];
__device__ float g_ea2[NET];
__device__ float g_h1[(size_t)NN*HID];
__device__ float g_hw[(size_t)NN*HID];
__device__ float g_h2[(size_t)NN*HID];
__device__ float g_t [(size_t)NN*HID];
__device__ float g_q [(size_t)NN*HID];
__device__ float g_pool[NB*HID];

// ---------------- helpers ----------------
__device__ __forceinline__ ull pk2(float lo, float hi) {
    ull r; asm("mov.b64 %0, {%1,%2};" : "=l"(r) : "f"(lo), "f"(hi)); return r;
}
__device__ __forceinline__ void fma2(ull& d, ull a, ull b) {
    asm("fma.rn.f32x2 %0, %1, %2, %0;" : "+l"(d) : "l"(a), "l"(b));
}
__device__ __forceinline__ void upk2(ull v, float& lo, float& hi) {
    asm("mov.b64 {%0,%1}, %2;" : "=f"(lo), "=f"(hi) : "l"(v));
}
// pack two floats -> bf16x2, low half = first arg
__device__ __forceinline__ u32 bfpack(float lo, float hi) {
    u32 r; asm("cvt.rn.bf16x2.f32 %0, %1, %2;" : "=r"(r) : "f"(hi), "f"(lo)); return r;
}
// hi/lo bf16 split of a float pair
__device__ __forceinline__ void split_pair(float x0, float x1, u32& ph, u32& pl) {
    ph = bfpack(x0, x1);
    float h0 = __uint_as_float(ph << 16);
    float h1 = __uint_as_float(ph & 0xFFFF0000u);
    pl = bfpack(x0 - h0, x1 - h1);
}
// m16n8k16 row.col bf16 -> f32 accumulate
__device__ __forceinline__ void mma16816(float* c, const u32* a, u32 b0, u32 b1) {
    asm volatile(
        "mma.sync.aligned.m16n8k16.row.col.f32.bf16.bf16.f32 "
        "{%0,%1,%2,%3}, {%4,%5,%6,%7}, {%8,%9}, {%0,%1,%2,%3};"
        : "+f"(c[0]), "+f"(c[1]), "+f"(c[2]), "+f"(c[3])
        : "r"(a[0]), "r"(a[1]), "r"(a[2]), "r"(a[3]), "r"(b0), "r"(b1));
}

// ---------------- prep ----------------
__global__ void prep_kernel(const float* __restrict__ node_tab,
                            const float* __restrict__ edge_tab,
                            const float* __restrict__ c1_w,
                            const float* __restrict__ c1_we,
                            const float* __restrict__ c1_ae,
                            const float* __restrict__ c2_we,
                            const float* __restrict__ c2_ae) {
    __shared__ float red[HID];
    int bid = blockIdx.x, tid = threadIdx.x;
    if (bid < NCAT) {
        float acc = 0.f;
        #pragma unroll 8
        for (int k = 0; k < EMB; k++) acc += node_tab[bid*EMB + k] * c1_w[k*HID + tid];
        g_P1[bid*HID + tid] = acc;
    } else {
        for (int combo = 0; combo < 2*NET; combo++) {
            int layer = combo >> 2, t = combo & 3;
            const float* We = layer ? c2_we : c1_we;
            const float* ae = layer ? c2_ae : c1_ae;
            float acc = 0.f;
            #pragma unroll 8
            for (int k = 0; k < EMB; k++) acc += edge_tab[t*EMB + k] * We[k*HID + tid];
            red[tid] = acc * ae[tid];
            __syncthreads();
            if (tid < 32) {
                float s = red[tid] + red[tid+32] + red[tid+64] + red[tid+96];
                #pragma unroll
                for (int o = 16; o; o >>= 1) s += __shfl_down_sync(0xffffffffu, s, o);
                if (tid == 0) { if (layer) g_ea2[t] = s; else g_ea1[t] = s; }
            }
            __syncthreads();
        }
    }
}

// ---------------- per-graph GAT layer ----------------
__global__ __launch_bounds__(256) void gat_kernel(
    const int* __restrict__ x,
    const int* __restrict__ edge_index,
    const int* __restrict__ edge_attr,
    const float* __restrict__ a_s,
    const float* __restrict__ a_d,
    const float* __restrict__ bias,
    int layer) {
    __shared__ float shh[NPG][HID];
    __shared__ float slog[EPG];
    __shared__ unsigned short ssrc[EPG];
    __shared__ float shs[NPG], shd[NPG];
    __shared__ int cnt[NPG], off[NPG], woff[NPG];
    __shared__ float shas[HID], shad[HID], shb[HID];
    __shared__ float shea[NET];
    __shared__ int codes[NPG];
    __shared__ float shpool[HID];

    int g = blockIdx.x, tid = threadIdx.x;
    int nbase = g * NPG, ebase = g * EPG;
    int lane = tid & 31, w = tid >> 5;

    if (tid < HID) { shas[tid] = a_s[tid]; shad[tid] = a_d[tid]; shb[tid] = bias[tid]; shpool[tid] = 0.f; }
    if (tid < NET) shea[tid] = layer ? g_ea2[tid] : g_ea1[tid];
    if (tid < NPG) { cnt[tid] = 0; if (layer == 0) codes[tid] = x[nbase + tid]; }
    __syncthreads();

    if (layer == 0) {
        for (int i = tid; i < NPG * (HID/4); i += 256) {
            int r = i >> 5, qq = i & 31;
            ((float4*)shh[r])[qq] = ((const float4*)(g_P1 + codes[r]*HID))[qq];
        }
    } else {
        const float4* src4 = (const float4*)(g_hw + (size_t)nbase * HID);
        for (int i = tid; i < NPG * (HID/4); i += 256)
            ((float4*)shh)[i] = src4[i];
    }
    __syncthreads();

    for (int r = w; r < NPG; r += 8) {
        float ss = 0.f, dd = 0.f;
        #pragma unroll
        for (int u = 0; u < 4; u++) {
            int c = lane + 32*u;
            float hv = shh[r][c];
            ss += hv * shas[c]; dd += hv * shad[c];
        }
        #pragma unroll
        for (int o = 16; o; o >>= 1) {
            ss += __shfl_down_sync(0xffffffffu, ss, o);
            dd += __shfl_down_sync(0xffffffffu, dd, o);
        }
        if (lane == 0) { shs[r] = ss; shd[r] = dd; }
    }

    for (int e = tid; e < EPG; e += 256) {
        int dl = edge_index[NEDGE + ebase + e] & (NPG - 1);
        atomicAdd(&cnt[dl], 1);
    }
    __syncthreads();
    if (tid == 0) {
        int run = 0;
        for (int i = 0; i < NPG; i++) { off[i] = run; woff[i] = run; run += cnt[i]; }
    }
    __syncthreads();

    for (int e = tid; e < EPG; e += 256) {
        int sl = edge_index[ebase + e] & (NPG - 1);
        int dl = edge_index[NEDGE + ebase + e] & (NPG - 1);
        int at = edge_attr[ebase + e];
        float lg = shs[sl] + shd[dl] + shea[at];
        lg = lg > 0.f ? lg : 0.2f * lg;
        int pos = atomicAdd(&woff[dl], 1);
        slog[pos] = lg;
        ssrc[pos] = (unsigned short)sl;
    }
    __syncthreads();

    float pacc[4] = {0.f, 0.f, 0.f, 0.f};
    int c0 = lane << 2;
    for (int dl = w; dl < NPG; dl += 8) {
        int st = off[dl], cn = cnt[dl];
        float m = -1e30f;
        for (int j = lane; j < cn; j += 32) m = fmaxf(m, slog[st + j]);
        #pragma unroll
        for (int o = 16; o; o >>= 1) m = fmaxf(m, __shfl_xor_sync(0xffffffffu, m, o));
        float den = 0.f;
        for (int j = lane; j < cn; j += 32) {
            float ex = expf(slog[st + j] - m);
            slog[st + j] = ex;
            den += ex;
        }
        #pragma unroll
        for (int o = 16; o; o >>= 1) den += __shfl_xor_sync(0xffffffffu, den, o);
        __syncwarp();
        float inv = 1.f / (den + 1e-16f);
        ull a0 = 0ull, a1 = 0ull;
        for (int j = 0; j < cn; j++) {
            float al = slog[st + j] * inv;
            ull pal = pk2(al, al);
            const ull* hr = (const ull*)&shh[ssrc[st + j]][c0];
            fma2(a0, pal, hr[0]);
            fma2(a1, pal, hr[1]);
        }
        float v0, v1, v2, v3;
        upk2(a0, v0, v1); upk2(a1, v2, v3);
        v0 += shb[c0]; v1 += shb[c0+1]; v2 += shb[c0+2]; v3 += shb[c0+3];
        if (layer == 0) { v0 = fmaxf(v0, 0.f); v1 = fmaxf(v1, 0.f); v2 = fmaxf(v2, 0.f); v3 = fmaxf(v3, 0.f); }
        float* outp = (layer == 0 ? g_h1 : g_h2) + (size_t)(nbase + dl) * HID;
        *(float4*)(outp + c0) = make_float4(v0, v1, v2, v3);
        if (layer) { pacc[0] += v0; pacc[1] += v1; pacc[2] += v2; pacc[3] += v3; }
    }
    if (layer) {
        atomicAdd(&shpool[c0],     pacc[0]);
        atomicAdd(&shpool[c0 + 1], pacc[1]);
        atomicAdd(&shpool[c0 + 2], pacc[2]);
        atomicAdd(&shpool[c0 + 3], pacc[3]);
        __syncthreads();
        if (tid < HID) g_pool[g * HID + tid] = shpool[tid];
    }
}

// ---------------- HMMA GEMM: out = post(A[N,128] @ W[128,CW]) ----------------
// B staged in smem in fragment order: sB[kstep][ntile][lane] = uint4{bh0,bh1,bl0,bl1}
// sel: 0 A=g_h1,out=g_hw | 1 A=g_h2,out=g_t | 2 A=g_h2,out=g_q | 3 A=g_t,out=param
#define GSMEM (8*16*32*16)   // 64 KB
__global__ __launch_bounds__(256, 1) void gemm_mma(
    const float* __restrict__ W, const float* __restrict__ bias,
    float* __restrict__ outParam, int CW, int doRelu, int mode, int sel) {
    extern __shared__ uint4 sB[];

    const float* A; float* out;
    if (sel == 0)      { A = g_h1; out = g_hw; }
    else if (sel == 1) { A = g_h2; out = g_t; }
    else if (sel == 2) { A = g_h2; out = g_q; }
    else               { A = g_t;  out = outParam; }

    int tid = threadIdx.x, wid = tid >> 5, lane = tid & 31;
    int rowbase = blockIdx.x * 128;

    // ---- stage B (hi/lo bf16 fragments) ----
    for (int i = tid; i < 8*16*32; i += 256) {
        int ks = i >> 9, rest = i & 511;
        int nt = rest >> 5, l = rest & 31;
        int k = ks * 16 + (l & 3) * 2;
        int n = nt * 8 + (l >> 2);
        float w00 = 0.f, w01 = 0.f, w10 = 0.f, w11 = 0.f;
        if (n < CW) {
            w00 = W[(size_t)k * CW + n];
            w01 = W[(size_t)(k + 1) * CW + n];
            w10 = W[(size_t)(k + 8) * CW + n];
            w11 = W[(size_t)(k + 9) * CW + n];
        }
        u32 bh0, bl0, bh1, bl1;
        split_pair(w00, w01, bh0, bl0);
        split_pair(w10, w11, bh1, bl1);
        sB[i] = make_uint4(bh0, bh1, bl0, bl1);
    }
    __syncthreads();

    // ---- per-warp 16x128 tile ----
    int r0 = rowbase + wid * 16 + (lane >> 2);
    int kc = (lane & 3) * 2;
    const float* pr0 = A + (size_t)r0 * HID;
    const float* pr8 = pr0 + 8 * (size_t)HID;

    float acc[16][4];
    #pragma unroll
    for (int nt = 0; nt < 16; nt++)
        #pragma unroll
        for (int j = 0; j < 4; j++) acc[nt][j] = 0.f;

    #pragma unroll
    for (int ks = 0; ks < 8; ks++) {
        int k0 = ks * 16 + kc;
        float2 v00 = *(const float2*)(pr0 + k0);
        float2 v10 = *(const float2*)(pr8 + k0);
        float2 v01 = *(const float2*)(pr0 + k0 + 8);
        float2 v11 = *(const float2*)(pr8 + k0 + 8);
        u32 ah[4], al[4];
        split_pair(v00.x, v00.y, ah[0], al[0]);
        split_pair(v10.x, v10.y, ah[1], al[1]);
        split_pair(v01.x, v01.y, ah[2], al[2]);
        split_pair(v11.x, v11.y, ah[3], al[3]);
        const uint4* bp = sB + (ks << 9) + lane;
        #pragma unroll
        for (int nt = 0; nt < 16; nt++) {
            uint4 b = bp[nt << 5];
            mma16816(acc[nt], ah, b.x, b.y);   // ah * bh
            mma16816(acc[nt], al, b.x, b.y);   // al * bh
            mma16816(acc[nt], ah, b.z, b.w);   // ah * bl
        }
    }

    // ---- epilogue ----
    int c_lo = (lane & 3) * 2;
    #pragma unroll
    for (int nt = 0; nt < 16; nt++) {
        int c = nt * 8 + c_lo;
        float x0 = acc[nt][0], x1 = acc[nt][1];   // row r0
        float x2 = acc[nt][2], x3 = acc[nt][3];   // row r0+8
        if (mode == 0) {
            if (bias) { float b0 = bias[c], b1 = bias[c+1]; x0 += b0; x1 += b1; x2 += b0; x3 += b1; }
            if (doRelu) { x0 = fmaxf(x0, 0.f); x1 = fmaxf(x1, 0.f); x2 = fmaxf(x2, 0.f); x3 = fmaxf(x3, 0.f); }
            *(float2*)(out + (size_t)r0 * HID + c)       = make_float2(x0, x1);
            *(float2*)(out + (size_t)(r0 + 8) * HID + c) = make_float2(x2, x3);
        } else {
            int g0 = r0 >> 6, l0 = r0 & 63;
            int r8 = r0 + 8;
            int g8 = r8 >> 6, l8 = r8 & 63;
            size_t b0p = (size_t)g0 * OUTW + 1 + (size_t)l0 * NOUT;
            size_t b8p = (size_t)g8 * OUTW + 1 + (size_t)l8 * NOUT;
            if (c < CW)     { float bb = bias[c];   out[b0p + c]     = x0 + bb; out[b8p + c]     = x2 + bb; }
            if (c + 1 < CW) { float bb = bias[c+1]; out[b0p + c + 1] = x1 + bb; out[b8p + c + 1] = x3 + bb; }
        }
    }
}

// ---------------- final: stop head + addedge head ----------------
__global__ __launch_bounds__(256) void final_kernel(
    const int* __restrict__ non_edges,
    const float* __restrict__ s_w1, const float* __restrict__ s_b1,
    const float* __restrict__ s_w2, const float* __restrict__ s_b2,
    const float* __restrict__ e_b1, const float* __restrict__ e_w2,
    const float* __restrict__ e_b2,
    float* __restrict__ out) {
    __shared__ float shq[NPG][HID];
    __shared__ float sheb[HID], shw2[HID], shp[HID], shz[HID];

    int g = blockIdx.x, tid = threadIdx.x;
    int lane = tid & 31, w = tid >> 5;

    const float4* src4 = (const float4*)(g_q + (size_t)g * NPG * HID);
    for (int i = tid; i < NPG * (HID/4); i += 256) ((float4*)shq)[i] = src4[i];
    if (tid < HID) { sheb[tid] = e_b1[tid]; shw2[tid] = e_w2[tid]; shp[tid] = g_pool[g * HID + tid]; }
    __syncthreads();

    if (tid < HID) {
        float acc = s_b1[tid];
        #pragma unroll 8
        for (int k = 0; k < HID; k++) acc += shp[k] * s_w1[k * HID + tid];
        shz[tid] = fmaxf(acc, 0.f);
    }
    __syncthreads();

    if (w == 0) {
        float s_ = 0.f;
        #pragma unroll
        for (int u = 0; u < 4; u++) s_ += shz[lane + 32*u] * s_w2[lane + 32*u];
        #pragma unroll
        for (int o = 16; o; o >>= 1) s_ += __shfl_down_sync(0xffffffffu, s_, o);
        if (lane == 0) out[(size_t)g * OUTW] = s_ + s_b2[0];
    }

    int nebase = g * NEPG;
    for (int ne = w; ne < NEPG; ne += 8) {
        int u = non_edges[(size_t)(nebase + ne) * 2]     & (NPG - 1);
        int v = non_edges[(size_t)(nebase + ne) * 2 + 1] & (NPG - 1);
        float acc = 0.f;
        #pragma unroll
        for (int uu = 0; uu < 4; uu++) {
            int c = lane + 32 * uu;
            float tv = shq[u][c] + shq[v][c] + sheb[c];
            tv = fmaxf(tv, 0.f);
            acc += tv * shw2[c];
        }
        #pragma unroll
        for (int o = 16; o; o >>= 1) acc += __shfl_down_sync(0xffffffffu, acc, o);
        if (lane == 0) out[(size_t)g * OUTW + 1 + NPG * NOUT + ne] = acc + e_b2[0];
    }
}

// ---------------- launch ----------------
extern "C" void kernel_launch(void* const* d_in, const int* in_sizes, int n_in,
                              void* d_out, int out_size) {
    const float* node_tab = (const float*)d_in[0];
    const float* edge_tab = (const float*)d_in[1];
    const float* c1_w  = (const float*)d_in[2];
    const float* c1_we = (const float*)d_in[3];
    const float* c1_as = (const float*)d_in[4];
    const float* c1_ad = (const float*)d_in[5];
    const float* c1_ae = (const float*)d_in[6];
    const float* c1_b  = (const float*)d_in[7];
    const float* c2_w  = (const float*)d_in[8];
    const float* c2_we = (const float*)d_in[9];
    const float* c2_as = (const float*)d_in[10];
    const float* c2_ad = (const float*)d_in[11];
    const float* c2_ae = (const float*)d_in[12];
    const float* c2_b  = (const float*)d_in[13];
    const float* s_w1  = (const float*)d_in[14];
    const float* s_b1  = (const float*)d_in[15];
    const float* s_w2  = (const float*)d_in[16];
    const float* s_b2  = (const float*)d_in[17];
    const float* n_w1  = (const float*)d_in[18];
    const float* n_b1  = (const float*)d_in[19];
    const float* n_w2  = (const float*)d_in[20];
    const float* n_b2  = (const float*)d_in[21];
    const float* e_w1  = (const float*)d_in[22];
    const float* e_b1  = (const float*)d_in[23];
    const float* e_w2  = (const float*)d_in[24];
    const float* e_b2  = (const float*)d_in[25];
    const int* x          = (const int*)d_in[26];
    const int* edge_index = (const int*)d_in[27];
    const int* edge_attr  = (const int*)d_in[28];
    const int* non_edges  = (const int*)d_in[29];
    float* out = (float*)d_out;

    cudaFuncSetAttribute(gemm_mma, cudaFuncAttributeMaxDynamicSharedMemorySize, GSMEM);

    prep_kernel<<<NCAT + 1, HID>>>(node_tab, edge_tab, c1_w, c1_we, c1_ae, c2_we, c2_ae);
    gat_kernel<<<NB, 256>>>(x, edge_index, edge_attr, c1_as, c1_ad, c1_b, 0);
    gemm_mma<<<NN/128, 256, GSMEM>>>(c2_w, nullptr, nullptr, HID, 0, 0, 0);   // g_hw
    gat_kernel<<<NB, 256>>>(x, edge_index, edge_attr, c2_as, c2_ad, c2_b, 1);
    gemm_mma<<<NN/128, 256, GSMEM>>>(n_w1, n_b1, nullptr, HID, 1, 0, 1);      // g_t
    gemm_mma<<<NN/128, 256, GSMEM>>>(e_w1, nullptr, nullptr, HID, 0, 0, 2);   // g_q
    gemm_mma<<<NN/128, 256, GSMEM>>>(n_w2, n_b2, out, NOUT, 0, 1, 3);         // addnode
    final_kernel<<<NB, 256>>>(non_edges, s_w1, s_b1, s_w2, s_b2, e_b1, e_w2, e_b2, out);
}

// round 5
// speedup vs baseline: 2.1791x; 1.2271x over previous
#include <cuda_runtime.h>
#include <cuda_bf16.h>
#include <cstdint>

#define NB   1024
#define NPG  64
#define EPG  1024
#define NEPG 256
#define NN   (NB*NPG)
#define NEDGE (NB*EPG)
#define EMB  64
#define HID  128
#define NCAT 100
#define NET  4
#define NOUT 101
#define OUTW (1 + NPG*NOUT + NEPG)   // 6721
#define STR  132                      // padded f32 tile row stride

typedef unsigned long long ull;
typedef unsigned int u32;
typedef unsigned short u16;

// ---------------- device scratch ----------------
__device__ float g_P1[NCAT*HID];
__device__ float g_ea[2][NET];
__device__ u16   g_pe[NEDGE];          // packed edges: src | dst<<6 | attr<<12
__device__ float g_hw[(size_t)NN*HID]; // K1 output (h1 @ c2_w)
__device__ uint4 g_Bf[4][4096];        // fragment-order split-bf16 weights: c2_w, n_w1, e_w1, n_w2

// ---------------- helpers ----------------
__device__ __forceinline__ ull pk2(float lo, float hi) {
    ull r; asm("mov.b64 %0, {%1,%2};" : "=l"(r) : "f"(lo), "f"(hi)); return r;
}
__device__ __forceinline__ void fma2(ull& d, ull a, ull b) {
    asm("fma.rn.f32x2 %0, %1, %2, %0;" : "+l"(d) : "l"(a), "l"(b));
}
__device__ __forceinline__ void upk2(ull v, float& lo, float& hi) {
    asm("mov.b64 {%0,%1}, %2;" : "=f"(lo), "=f"(hi) : "l"(v));
}
__device__ __forceinline__ u32 bfpack(float lo, float hi) {
    u32 r; asm("cvt.rn.bf16x2.f32 %0, %1, %2;" : "=r"(r) : "f"(hi), "f"(lo)); return r;
}
__device__ __forceinline__ void split_pair(float x0, float x1, u32& ph, u32& pl) {
    ph = bfpack(x0, x1);
    float h0 = __uint_as_float(ph << 16);
    float h1 = __uint_as_float(ph & 0xFFFF0000u);
    pl = bfpack(x0 - h0, x1 - h1);
}
__device__ __forceinline__ void mma16816(float* c, const u32* a, u32 b0, u32 b1) {
    asm volatile(
        "mma.sync.aligned.m16n8k16.row.col.f32.bf16.bf16.f32 "
        "{%0,%1,%2,%3}, {%4,%5,%6,%7}, {%8,%9}, {%0,%1,%2,%3};"
        : "+f"(c[0]), "+f"(c[1]), "+f"(c[2]), "+f"(c[3])
        : "r"(a[0]), "r"(a[1]), "r"(a[2]), "r"(a[3]), "r"(b0), "r"(b1));
}

// 64x128 @ 128x128 split-bf16 HMMA; A f32 in smem (stride STR), B fragments in global.
// warp w: rows (w&3)*16..+16, col half (w>>2)*64. acc[nt][4].
__device__ __forceinline__ void mma_block(const float* __restrict__ sA,
                                          const uint4* __restrict__ Bf,
                                          int wid, int lane, float acc[8][4]) {
    int rt = wid & 3, ch = wid >> 2;
    int r0 = rt * 16 + (lane >> 2);
    int kc = (lane & 3) * 2;
    const float* pr0 = sA + r0 * STR;
    const float* pr8 = sA + (r0 + 8) * STR;
    #pragma unroll
    for (int nt = 0; nt < 8; nt++)
        #pragma unroll
        for (int j = 0; j < 4; j++) acc[nt][j] = 0.f;
    #pragma unroll
    for (int ks = 0; ks < 8; ks++) {
        int k0 = ks * 16 + kc;
        float2 v00 = *(const float2*)(pr0 + k0);
        float2 v10 = *(const float2*)(pr8 + k0);
        float2 v01 = *(const float2*)(pr0 + k0 + 8);
        float2 v11 = *(const float2*)(pr8 + k0 + 8);
        u32 ah[4], al[4];
        split_pair(v00.x, v00.y, ah[0], al[0]);
        split_pair(v10.x, v10.y, ah[1], al[1]);
        split_pair(v01.x, v01.y, ah[2], al[2]);
        split_pair(v11.x, v11.y, ah[3], al[3]);
        const uint4* bp = Bf + (ks << 9) + (ch << 8) + lane;
        #pragma unroll
        for (int nt = 0; nt < 8; nt++) {
            uint4 b = bp[nt << 5];
            mma16816(acc[nt], ah, b.x, b.y);
            mma16816(acc[nt], al, b.x, b.y);
            mma16816(acc[nt], ah, b.z, b.w);
        }
    }
}

// ---------------- attention (per graph, in smem) ----------------
__device__ __forceinline__ void attention_block(
    const float* __restrict__ shh, float* __restrict__ shO,
    float* slog, u16* ssrc, int* cnt, int* offv, int* woff,
    float* shs, float* shd,
    const float* shas, const float* shad, const float* shb, const float* shea,
    const u16* __restrict__ pe, int doRelu, float* shpool, int tid)
{
    int lane = tid & 31, w = tid >> 5;

    // per-node attention scalars
    for (int r = w; r < NPG; r += 8) {
        float ss = 0.f, dd = 0.f;
        #pragma unroll
        for (int u = 0; u < 4; u++) {
            int c = lane + 32 * u;
            float hv = shh[r * STR + c];
            ss += hv * shas[c]; dd += hv * shad[c];
        }
        #pragma unroll
        for (int o = 16; o; o >>= 1) {
            ss += __shfl_down_sync(0xffffffffu, ss, o);
            dd += __shfl_down_sync(0xffffffffu, dd, o);
        }
        if (lane == 0) { shs[r] = ss; shd[r] = dd; }
    }

    // count per dst
    for (int e = tid; e < EPG; e += 256)
        atomicAdd(&cnt[(pe[e] >> 6) & 63], 1);
    __syncthreads();
    if (tid == 0) {
        int run = 0;
        for (int i = 0; i < NPG; i++) { offv[i] = run; woff[i] = run; run += cnt[i]; }
    }
    __syncthreads();

    // logits + counting sort
    for (int e = tid; e < EPG; e += 256) {
        unsigned p = pe[e];
        int sl = p & 63, dl = (p >> 6) & 63, at = p >> 12;
        float lg = shs[sl] + shd[dl] + shea[at];
        lg = lg > 0.f ? lg : 0.2f * lg;
        int pos = atomicAdd(&woff[dl], 1);
        slog[pos] = lg;
        ssrc[pos] = (u16)sl;
    }
    __syncthreads();

    // per-dst softmax + aggregate
    int c0 = lane << 2;
    for (int dl = w; dl < NPG; dl += 8) {
        int st = offv[dl], cn = cnt[dl];
        float m = -1e30f;
        for (int j = lane; j < cn; j += 32) m = fmaxf(m, slog[st + j]);
        #pragma unroll
        for (int o = 16; o; o >>= 1) m = fmaxf(m, __shfl_xor_sync(0xffffffffu, m, o));
        float den = 0.f;
        for (int j = lane; j < cn; j += 32) {
            float ex = expf(slog[st + j] - m);
            slog[st + j] = ex;
            den += ex;
        }
        #pragma unroll
        for (int o = 16; o; o >>= 1) den += __shfl_xor_sync(0xffffffffu, den, o);
        __syncwarp();
        float inv = 1.f / (den + 1e-16f);
        ull a0 = 0ull, a1 = 0ull;
        for (int j = 0; j < cn; j++) {
            float al = slog[st + j] * inv;
            ull pal = pk2(al, al);
            const ull* hr = (const ull*)&shh[ssrc[st + j] * STR + c0];
            fma2(a0, pal, hr[0]);
            fma2(a1, pal, hr[1]);
        }
        float v0, v1, v2, v3;
        upk2(a0, v0, v1); upk2(a1, v2, v3);
        v0 += shb[c0]; v1 += shb[c0+1]; v2 += shb[c0+2]; v3 += shb[c0+3];
        if (doRelu) { v0 = fmaxf(v0,0.f); v1 = fmaxf(v1,0.f); v2 = fmaxf(v2,0.f); v3 = fmaxf(v3,0.f); }
        *(float4*)&shO[dl * STR + c0] = make_float4(v0, v1, v2, v3);
        if (shpool) {
            atomicAdd(&shpool[c0],   v0);
            atomicAdd(&shpool[c0+1], v1);
            atomicAdd(&shpool[c0+2], v2);
            atomicAdd(&shpool[c0+3], v3);
        }
    }
}

// ---------------- prep ----------------
__global__ void prep_main(const float* __restrict__ node_tab,
                          const float* __restrict__ edge_tab,
                          const float* __restrict__ c1_w,
                          const float* __restrict__ c1_we,
                          const float* __restrict__ c1_ae,
                          const float* __restrict__ c2_we,
                          const float* __restrict__ c2_ae) {
    __shared__ float red[HID];
    int bid = blockIdx.x, tid = threadIdx.x;
    if (bid < NCAT) {
        float acc = 0.f;
        #pragma unroll 8
        for (int k = 0; k < EMB; k++) acc += node_tab[bid*EMB + k] * c1_w[k*HID + tid];
        g_P1[bid*HID + tid] = acc;
    } else {
        for (int combo = 0; combo < 2*NET; combo++) {
            int layer = combo >> 2, t = combo & 3;
            const float* We = layer ? c2_we : c1_we;
            const float* ae = layer ? c2_ae : c1_ae;
            float acc = 0.f;
            #pragma unroll 8
            for (int k = 0; k < EMB; k++) acc += edge_tab[t*EMB + k] * We[k*HID + tid];
            red[tid] = acc * ae[tid];
            __syncthreads();
            if (tid < 32) {
                float s = red[tid] + red[tid+32] + red[tid+64] + red[tid+96];
                #pragma unroll
                for (int o = 16; o; o >>= 1) s += __shfl_down_sync(0xffffffffu, s, o);
                if (tid == 0) g_ea[layer][t] = s;
            }
            __syncthreads();
        }
    }
}

__global__ void prep_w(const float* __restrict__ w0, const float* __restrict__ w1,
                       const float* __restrict__ w2, const float* __restrict__ w3) {
    int b = blockIdx.x, tid = threadIdx.x;
    const float* W = (b == 0) ? w0 : (b == 1) ? w1 : (b == 2) ? w2 : w3;
    int CW = (b == 3) ? NOUT : HID;
    for (int i = tid; i < 4096; i += 256) {
        int ks = i >> 9, rest = i & 511;
        int nt = rest >> 5, l = rest & 31;
        int k = ks * 16 + (l & 3) * 2;
        int n = nt * 8 + (l >> 2);
        float w00=0.f, w01=0.f, w10=0.f, w11=0.f;
        if (n < CW) {
            w00 = W[(size_t)k * CW + n];
            w01 = W[(size_t)(k+1) * CW + n];
            w10 = W[(size_t)(k+8) * CW + n];
            w11 = W[(size_t)(k+9) * CW + n];
        }
        u32 bh0, bl0, bh1, bl1;
        split_pair(w00, w01, bh0, bl0);
        split_pair(w10, w11, bh1, bl1);
        g_Bf[b][i] = make_uint4(bh0, bh1, bl0, bl1);
    }
}

__global__ void prep_e(const int* __restrict__ edge_index, const int* __restrict__ edge_attr) {
    for (int e = blockIdx.x * blockDim.x + threadIdx.x; e < NEDGE; e += gridDim.x * blockDim.x) {
        int sl = edge_index[e] & 63;
        int dl = edge_index[NEDGE + e] & 63;
        int at = edge_attr[e];
        g_pe[e] = (u16)(sl | (dl << 6) | (at << 12));
    }
}

// ---------------- K1: GAT1 + (h1 @ c2_w) ----------------
struct K1S {
    float shh[NPG*STR];
    float sh1[NPG*STR];
    float slog[EPG];
    u16   ssrc[EPG];
    int   cnt[NPG], offv[NPG], woff[NPG];
    float shs[NPG], shd[NPG];
    float shas[HID], shad[HID], shb[HID];
    float shea[NET];
    int   codes[NPG];
};
__global__ __launch_bounds__(256) void k1(
    const int* __restrict__ x,
    const float* __restrict__ a_s, const float* __restrict__ a_d,
    const float* __restrict__ bias) {
    extern __shared__ char smraw[];
    K1S& S = *(K1S*)smraw;
    int g = blockIdx.x, tid = threadIdx.x;
    int lane = tid & 31, wid = tid >> 5;

    if (tid < HID) { S.shas[tid] = a_s[tid]; S.shad[tid] = a_d[tid]; S.shb[tid] = bias[tid]; }
    if (tid < NET) S.shea[tid] = g_ea[0][tid];
    if (tid < NPG) { S.cnt[tid] = 0; S.codes[tid] = x[g * NPG + tid]; }
    __syncthreads();
    for (int i = tid; i < NPG * 32; i += 256) {
        int r = i >> 5, qq = i & 31;
        *(float4*)&S.shh[r * STR + qq * 4] = ((const float4*)(g_P1 + S.codes[r] * HID))[qq];
    }
    __syncthreads();

    attention_block(S.shh, S.sh1, S.slog, S.ssrc, S.cnt, S.offv, S.woff,
                    S.shs, S.shd, S.shas, S.shad, S.shb, S.shea,
                    g_pe + g * EPG, 1, nullptr, tid);
    __syncthreads();

    float acc[8][4];
    mma_block(S.sh1, g_Bf[0], wid, lane, acc);
    int rt = wid & 3, ch = wid >> 2;
    int r0 = rt * 16 + (lane >> 2), kc = (lane & 3) * 2;
    float* o0 = g_hw + (size_t)(g * NPG + r0) * HID;
    float* o8 = o0 + 8 * (size_t)HID;
    #pragma unroll
    for (int nt = 0; nt < 8; nt++) {
        int c = ch * 64 + nt * 8 + kc;
        *(float2*)(o0 + c) = make_float2(acc[nt][0], acc[nt][1]);
        *(float2*)(o8 + c) = make_float2(acc[nt][2], acc[nt][3]);
    }
}

// ---------------- K2: GAT2 + heads ----------------
struct K2S {
    float shh[NPG*STR];    // input g_hw tile; later reused for q
    float sh2[NPG*STR];    // h2
    float sht[NPG*STR];    // t
    float slog[EPG];
    u16   ssrc[EPG];
    int   cnt[NPG], offv[NPG], woff[NPG];
    float shs[NPG], shd[NPG];
    float shas[HID], shad[HID], shb[HID];
    float shb1[HID], sheb1[HID], shew2[HID];
    float shpool[HID], shz[HID];
    float shea[NET];
};
__global__ __launch_bounds__(256) void k2(
    const float* __restrict__ a_s, const float* __restrict__ a_d,
    const float* __restrict__ bias,                         // c2_b
    const float* __restrict__ n_b1, const float* __restrict__ n_b2,
    const float* __restrict__ e_b1, const float* __restrict__ e_w2,
    const float* __restrict__ e_b2,
    const float* __restrict__ s_w1, const float* __restrict__ s_b1,
    const float* __restrict__ s_w2, const float* __restrict__ s_b2,
    const int* __restrict__ non_edges,
    float* __restrict__ out) {
    extern __shared__ char smraw[];
    K2S& S = *(K2S*)smraw;
    int g = blockIdx.x, tid = threadIdx.x;
    int lane = tid & 31, wid = tid >> 5;

    if (tid < HID) {
        S.shas[tid] = a_s[tid]; S.shad[tid] = a_d[tid]; S.shb[tid] = bias[tid];
        S.shb1[tid] = n_b1[tid]; S.sheb1[tid] = e_b1[tid]; S.shew2[tid] = e_w2[tid];
        S.shpool[tid] = 0.f;
    }
    if (tid < NET) S.shea[tid] = g_ea[1][tid];
    if (tid < NPG) S.cnt[tid] = 0;
    const float4* src4 = (const float4*)(g_hw + (size_t)g * NPG * HID);
    __syncthreads();
    for (int i = tid; i < NPG * 32; i += 256) {
        int r = i >> 5, qq = i & 31;
        *(float4*)&S.shh[r * STR + qq * 4] = src4[i];
    }
    __syncthreads();

    attention_block(S.shh, S.sh2, S.slog, S.ssrc, S.cnt, S.offv, S.woff,
                    S.shs, S.shd, S.shas, S.shad, S.shb, S.shea,
                    g_pe + g * EPG, 0, S.shpool, tid);
    __syncthreads();   // sh2 + pool final; shh free from here

    int rt = wid & 3, ch = wid >> 2;
    int r0 = rt * 16 + (lane >> 2), kc = (lane & 3) * 2;
    float acc[8][4];

    // t = relu(h2 @ n_w1 + b1) -> sht
    mma_block(S.sh2, g_Bf[1], wid, lane, acc);
    #pragma unroll
    for (int nt = 0; nt < 8; nt++) {
        int c = ch * 64 + nt * 8 + kc;
        float b0 = S.shb1[c], b1v = S.shb1[c+1];
        *(float2*)&S.sht[r0 * STR + c] =
            make_float2(fmaxf(acc[nt][0] + b0, 0.f), fmaxf(acc[nt][1] + b1v, 0.f));
        *(float2*)&S.sht[(r0 + 8) * STR + c] =
            make_float2(fmaxf(acc[nt][2] + b0, 0.f), fmaxf(acc[nt][3] + b1v, 0.f));
    }
    // q = h2 @ e_w1 -> shh
    mma_block(S.sh2, g_Bf[2], wid, lane, acc);
    #pragma unroll
    for (int nt = 0; nt < 8; nt++) {
        int c = ch * 64 + nt * 8 + kc;
        *(float2*)&S.shh[r0 * STR + c] = make_float2(acc[nt][0], acc[nt][1]);
        *(float2*)&S.shh[(r0 + 8) * STR + c] = make_float2(acc[nt][2], acc[nt][3]);
    }
    __syncthreads();   // sht, shh(q) complete

    // addnode = t @ n_w2 + n_b2 -> out (strided)
    mma_block(S.sht, g_Bf[3], wid, lane, acc);
    size_t gbase = (size_t)g * OUTW + 1;
    #pragma unroll
    for (int nt = 0; nt < 8; nt++) {
        int c = ch * 64 + nt * 8 + kc;
        size_t b0p = gbase + (size_t)r0 * NOUT;
        size_t b8p = gbase + (size_t)(r0 + 8) * NOUT;
        if (c < NOUT)     { float bb = n_b2[c];   out[b0p + c]   = acc[nt][0] + bb; out[b8p + c]   = acc[nt][2] + bb; }
        if (c + 1 < NOUT) { float bb = n_b2[c+1]; out[b0p + c+1] = acc[nt][1] + bb; out[b8p + c+1] = acc[nt][3] + bb; }
    }

    // addedge head (q in shh)
    int nebase = g * NEPG;
    float eb2 = e_b2[0];
    for (int ne = wid; ne < NEPG; ne += 8) {
        int u = non_edges[(size_t)(nebase + ne) * 2]     & 63;
        int v = non_edges[(size_t)(nebase + ne) * 2 + 1] & 63;
        float acc2 = 0.f;
        #pragma unroll
        for (int uu = 0; uu < 4; uu++) {
            int c = lane + 32 * uu;
            float tv = S.shh[u * STR + c] + S.shh[v * STR + c] + S.sheb1[c];
            tv = fmaxf(tv, 0.f);
            acc2 += tv * S.shew2[c];
        }
        #pragma unroll
        for (int o = 16; o; o >>= 1) acc2 += __shfl_down_sync(0xffffffffu, acc2, o);
        if (lane == 0) out[(size_t)g * OUTW + 1 + NPG * NOUT + ne] = acc2 + eb2;
    }

    // stop head (pool in shpool)
    if (tid < HID) {
        float acc3 = s_b1[tid];
        #pragma unroll 8
        for (int k = 0; k < HID; k++) acc3 += S.shpool[k] * s_w1[k * HID + tid];
        S.shz[tid] = fmaxf(acc3, 0.f);
    }
    __syncthreads();
    if (wid == 0) {
        float s_ = 0.f;
        #pragma unroll
        for (int u = 0; u < 4; u++) s_ += S.shz[lane + 32*u] * s_w2[lane + 32*u];
        #pragma unroll
        for (int o = 16; o; o >>= 1) s_ += __shfl_down_sync(0xffffffffu, s_, o);
        if (lane == 0) out[(size_t)g * OUTW] = s_ + s_b2[0];
    }
}

// ---------------- launch ----------------
extern "C" void kernel_launch(void* const* d_in, const int* in_sizes, int n_in,
                              void* d_out, int out_size) {
    const float* node_tab = (const float*)d_in[0];
    const float* edge_tab = (const float*)d_in[1];
    const float* c1_w  = (const float*)d_in[2];
    const float* c1_we = (const float*)d_in[3];
    const float* c1_as = (const float*)d_in[4];
    const float* c1_ad = (const float*)d_in[5];
    const float* c1_ae = (const float*)d_in[6];
    const float* c1_b  = (const float*)d_in[7];
    const float* c2_w  = (const float*)d_in[8];
    const float* c2_we = (const float*)d_in[9];
    const float* c2_as = (const float*)d_in[10];
    const float* c2_ad = (const float*)d_in[11];
    const float* c2_ae = (const float*)d_in[12];
    const float* c2_b  = (const float*)d_in[13];
    const float* s_w1  = (const float*)d_in[14];
    const float* s_b1  = (const float*)d_in[15];
    const float* s_w2  = (const float*)d_in[16];
    const float* s_b2  = (const float*)d_in[17];
    const float* n_w1  = (const float*)d_in[18];
    const float* n_b1  = (const float*)d_in[19];
    const float* n_w2  = (const float*)d_in[20];
    const float* n_b2  = (const float*)d_in[21];
    const float* e_w1  = (const float*)d_in[22];
    const float* e_b1  = (const float*)d_in[23];
    const float* e_w2  = (const float*)d_in[24];
    const float* e_b2  = (const float*)d_in[25];
    const int* x          = (const int*)d_in[26];
    const int* edge_index = (const int*)d_in[27];
    const int* edge_attr  = (const int*)d_in[28];
    const int* non_edges  = (const int*)d_in[29];
    float* out = (float*)d_out;

    cudaFuncSetAttribute(k1, cudaFuncAttributeMaxDynamicSharedMemorySize, (int)sizeof(K1S));
    cudaFuncSetAttribute(k2, cudaFuncAttributeMaxDynamicSharedMemorySize, (int)sizeof(K2S));

    prep_main<<<NCAT + 1, HID>>>(node_tab, edge_tab, c1_w, c1_we, c1_ae, c2_we, c2_ae);
    prep_w<<<4, 256>>>(c2_w, n_w1, e_w1, n_w2);
    prep_e<<<512, 256>>>(edge_index, edge_attr);
    k1<<<NB, 256, sizeof(K1S)>>>(x, c1_as, c1_ad, c1_b);
    k2<<<NB, 256, sizeof(K2S)>>>(c2_as, c2_ad, c2_b, n_b1, n_b2, e_b1, e_w2, e_b2,
                                 s_w1, s_b1, s_w2, s_b2, non_edges, out);
}